// round 10
// baseline (speedup 1.0000x reference)
#include <cuda_runtime.h>
#include <cstdint>

// out[i, :] = table[idx[i], :]
// table: [2,000,000 x 128] f32.  idx: [1,048,576] int32 OR int64 (JAX x64 trap:
// jnp.int64 silently becomes int32 when jax_enable_x64 is off). A tiny probe
// kernel detects the actual width at runtime; the gather branches on a
// __device__ flag (warp-uniform load, L2-broadcast — noise).
//
// Gather: one warp handles FOUR adjacent rows. 32 lanes x float4 = 512 B = one
// row. All four index loads, then all four row gathers, are issued before any
// store, so each warp keeps 4 independent 4-line (512 B) gathers in flight
// (MLP=4) — the key lever for a latency-dominated random gather. Reads are 4
// contiguous 128B lines per row (coalesced); writes stream to 4 adjacent rows
// with st.global.cs (evict-first) so the write-once output does not thrash the
// L2 lines that the randomly-gathered table wants.

static constexpr long long NUM_NODES = 2000000;
static constexpr int EMB_DIM = 128;
static constexpr int VEC_PER_ROW = EMB_DIM / 4;   // 32 float4 lanes per row
static constexpr int ROWS_PER_WARP = 4;

__device__ int g_idx_is_i64;   // 1 = indices are int64, 0 = int32

// Probe the first 64 values interpreted as int64. Real int64 indices all lie
// in [0, NUM_NODES). Int32 data misread as int64 packs two indices per value
// (lo + hi*2^32); for uniform random indices the chance all 64 probed values
// have hi==0 is ~0, so any out-of-range value => int32. Reads 512 B, safe for
// either layout (idx buffer is >= 4 MiB).
__global__ void detect_idx_dtype_kernel(const long long* __restrict__ idx64)
{
    if (threadIdx.x == 0 && blockIdx.x == 0) {
        int is64 = 1;
        #pragma unroll 1
        for (int i = 0; i < 64; ++i) {
            long long v = idx64[i];
            if (v < 0 || v >= NUM_NODES) { is64 = 0; break; }
        }
        g_idx_is_i64 = is64;
    }
}

__device__ __forceinline__ long long load_row_index(const void* idx_raw,
                                                    int i, int is64)
{
    long long row = is64 ? __ldg(((const long long*)idx_raw) + i)
                         : (long long)__ldg(((const int*)idx_raw) + i);
    // Clamp: a wrong dtype theory becomes rel_err, not an illegal access.
    if (row < 0) row = 0;
    if (row >= NUM_NODES) row = NUM_NODES - 1;
    return row;
}

__global__ __launch_bounds__(256)
void gather_rows_kernel(const float4* __restrict__ table,
                        const void* __restrict__ idx_raw,
                        float4* __restrict__ out,
                        int num_ids)
{
    const int warp_id = (blockIdx.x * blockDim.x + threadIdx.x) >> 5;
    const int lane    = threadIdx.x & 31;
    const int i0      = warp_id * ROWS_PER_WARP;
    if (i0 >= num_ids) return;

    const int is64 = g_idx_is_i64;

    // Front-batch all index loads (warp-uniform broadcasts).
    long long r[ROWS_PER_WARP];
    #pragma unroll
    for (int k = 0; k < ROWS_PER_WARP; ++k) {
        const int i = i0 + k;
        r[k] = (i < num_ids) ? load_row_index(idx_raw, i, is64) : 0;
    }

    // Front-batch all row gathers: 4 independent 512 B loads in flight.
    float4 v[ROWS_PER_WARP];
    #pragma unroll
    for (int k = 0; k < ROWS_PER_WARP; ++k)
        v[k] = __ldg(&table[r[k] * (long long)VEC_PER_ROW + lane]);

    // Streaming (evict-first) stores to 4 adjacent output rows.
    float4* o = out + (long long)i0 * VEC_PER_ROW + lane;
    #pragma unroll
    for (int k = 0; k < ROWS_PER_WARP; ++k)
        if (i0 + k < num_ids) __stcs(&o[(long long)k * VEC_PER_ROW], v[k]);
}

extern "C" void kernel_launch(void* const* d_in, const int* in_sizes, int n_in,
                              void* d_out, int out_size)
{
    const float4* table = (const float4*)d_in[0];
    const void*   idx   = d_in[1];
    float4*       out   = (float4*)d_out;

    const int num_ids = in_sizes[1];          // 1,048,576

    detect_idx_dtype_kernel<<<1, 32>>>((const long long*)idx);

    const int threads = 256;                                   // 8 warps/block
    const int rows_per_block = (threads / 32) * ROWS_PER_WARP; // 32 rows
    const int blocks = (num_ids + rows_per_block - 1) / rows_per_block;
    gather_rows_kernel<<<blocks, threads>>>(table, idx, out, num_ids);
}